// round 1
// baseline (speedup 1.0000x reference)
#include <cuda_runtime.h>

#define N_NODES_C 50000
#define D_FEAT 64
#define D_OUT 64
#define N_REL 8
#define N_BASES 4
#define K_DIM (D_FEAT * N_BASES)   /* 256 */
#define NODE_TILE 16
#define TBLOCK 256

// Scratch: transformed node features y[n][o]  (12.8 MB, __device__ global per rules)
__device__ float g_y[(size_t)N_NODES_C * D_OUT];

// ---------------------------------------------------------------------------
// Kernel 1: per-node transform  y = (x @_r w_rel) @_{i,b} w_bases
//   z[n, i, b] = sum_r x[n,i,r] * w_rel[r,b]
//   y[n, o]    = sum_{i,b} z[n,i,b] * w_bases[b,i,o]
// smem: wb_s [256][64] (k = i*4+b major), z_s [16][256], wrel_s [8][4]
// ---------------------------------------------------------------------------
extern "C" __global__ void __launch_bounds__(TBLOCK, 2)
rgcn_transform(const float* __restrict__ x,
               const float* __restrict__ w_bases,
               const float* __restrict__ w_rel,
               int n_nodes)
{
    extern __shared__ float smem[];
    float* wb_s   = smem;                        // 16384 floats
    float* z_s    = smem + K_DIM * D_OUT;        // 4096 floats
    float* wrel_s = z_s + NODE_TILE * K_DIM;     // 32 floats

    const int t = threadIdx.x;

    if (t < N_REL * N_BASES) wrel_s[t] = w_rel[t];
    // wb_s[(i*4+b)*64 + o] = w_bases[b*64*64 + i*64 + o]
    for (int idx = t; idx < K_DIM * D_OUT; idx += TBLOCK) {
        int k = idx >> 6, o = idx & 63;
        int b = k & 3,   i = k >> 2;
        wb_s[idx] = w_bases[(b * D_FEAT + i) * D_OUT + o];
    }
    __syncthreads();

    const int n_tiles = n_nodes / NODE_TILE;     // 50000/16 = 3125, exact
    for (int tile = blockIdx.x; tile < n_tiles; tile += gridDim.x) {
        const int node0 = tile * NODE_TILE;

        // ---- Phase A: z tile -------------------------------------------
        #pragma unroll
        for (int pp = 0; pp < (NODE_TILE * D_FEAT) / TBLOCK; pp++) {
            int p = t + pp * TBLOCK;             // (n,i) pair, 0..1023
            int n = p >> 6;
            int i = p & 63;
            const float4* xr = (const float4*)(x + ((size_t)(node0 + n) * D_FEAT + i) * N_REL);
            float4 x0 = xr[0];
            float4 x1 = xr[1];
            float zz[4];
            #pragma unroll
            for (int b = 0; b < 4; b++) {
                zz[b] = x0.x * wrel_s[0*4+b] + x0.y * wrel_s[1*4+b]
                      + x0.z * wrel_s[2*4+b] + x0.w * wrel_s[3*4+b]
                      + x1.x * wrel_s[4*4+b] + x1.y * wrel_s[5*4+b]
                      + x1.z * wrel_s[6*4+b] + x1.w * wrel_s[7*4+b];
            }
            *((float4*)(z_s + n * K_DIM + i * 4)) = make_float4(zz[0], zz[1], zz[2], zz[3]);
        }
        __syncthreads();

        // ---- Phase B: y tile = z @ wb ----------------------------------
        {
            const int nl  = t >> 4;              // node within tile (0..15)
            const int sub = t & 15;              // output group (4 outs each)
            const float*  zrow = z_s + nl * K_DIM;
            const float4* wb4  = (const float4*)wb_s;
            float4 acc = make_float4(0.f, 0.f, 0.f, 0.f);
            #pragma unroll 8
            for (int k = 0; k < K_DIM; k++) {
                float  zv = zrow[k];
                float4 wv = wb4[k * 16 + sub];
                acc.x += zv * wv.x;
                acc.y += zv * wv.y;
                acc.z += zv * wv.z;
                acc.w += zv * wv.w;
            }
            *((float4*)(g_y + (size_t)(node0 + nl) * D_OUT + sub * 4)) = acc;
        }
        __syncthreads();  // protect z_s before next tile
    }
}

// ---------------------------------------------------------------------------
// Kernel 2: edge scatter  out[dst] += w_e * y[src]
// 16 threads per edge, each handles one float4 slice; vectorized red.
// ---------------------------------------------------------------------------
extern "C" __global__ void rgcn_scatter(const int*   __restrict__ esrc,
                                        const int*   __restrict__ edst,
                                        const float* __restrict__ ew,
                                        float*       __restrict__ out,
                                        int n_edges)
{
    int idx = blockIdx.x * blockDim.x + threadIdx.x;
    if (idx >= n_edges * 16) return;
    int e    = idx >> 4;
    int part = idx & 15;
    int s = esrc[e];
    int d = edst[e];
    float w = ew[e];
    float4 v = ((const float4*)(g_y + (size_t)s * D_OUT))[part];
    float* p = out + (size_t)d * D_OUT + part * 4;
    asm volatile("red.global.add.v4.f32 [%0], {%1, %2, %3, %4};"
                 :: "l"(p), "f"(v.x * w), "f"(v.y * w), "f"(v.z * w), "f"(v.w * w)
                 : "memory");
}

// ---------------------------------------------------------------------------
extern "C" void kernel_launch(void* const* d_in, const int* in_sizes, int n_in,
                              void* d_out, int out_size)
{
    const float* x    = (const float*)d_in[0];
    const int*   esrc = (const int*)  d_in[1];
    const int*   edst = (const int*)  d_in[2];
    const float* ew   = (const float*)d_in[3];
    const float* wb   = (const float*)d_in[4];
    const float* wrel = (const float*)d_in[5];
    float* out = (float*)d_out;

    const int n_nodes = in_sizes[0] / (D_FEAT * N_REL);
    const int n_edges = in_sizes[1];

    const int smem_bytes = (K_DIM * D_OUT + NODE_TILE * K_DIM + N_REL * N_BASES) * sizeof(float);
    cudaFuncSetAttribute(rgcn_transform, cudaFuncAttributeMaxDynamicSharedMemorySize, smem_bytes);

    // out must be zero before atomic accumulation
    cudaMemsetAsync(d_out, 0, (size_t)out_size * sizeof(float), 0);

    rgcn_transform<<<296, TBLOCK, smem_bytes>>>(x, wb, wrel, n_nodes);

    int total = n_edges * 16;
    int blocks = (total + TBLOCK - 1) / TBLOCK;
    rgcn_scatter<<<blocks, TBLOCK>>>(esrc, edst, ew, out, n_edges);
}